// round 15
// baseline (speedup 1.0000x reference)
#include <cuda_runtime.h>
#include <math.h>

#define NB   4
#define CPc  256
#define PLc  64
#define NQc  2304

typedef unsigned long long ull;

__constant__ int  d_Mi[5]    = {2304, 2304, 576, 144, 36};
__constant__ long d_PGoff[5] = {0L,
                                (long)NB * 128 * 2304,
                                (long)NB * 128 * (2304 + 2304),
                                (long)NB * 128 * (2304 + 2304 + 576),
                                (long)NB * 128 * (2304 + 2304 + 576 + 144)};
#define PG_TOTAL ((long)NB * 128 * (2304 + 2304 + 576 + 144 + 36))
#define OSZ ((long)NB * NQc * PLc)
#define CNTF ((float)(NB * NQc))

// Gs column swizzle (16B-preserving)
#define GSW(m, c) ((c) ^ (((((m) >> 2) & 15)) << 2))

// ---------------------------------------------------------------------------
// Scratch
// ---------------------------------------------------------------------------
__device__ float g_T  [NB * PLc * NQc];
__device__ float g_PG [NB * 128 * (2304 + 2304 + 576 + 144 + 36)];
__device__ float g_O  [5 * NB * NQc * PLc];
__device__ float g_cov[5 * 4160];
__device__ float g_Wq [CPc * 320];
__device__ float g_cst[5 * CPc];

// ---------------------------------------------------------------------------
// Helpers
// ---------------------------------------------------------------------------
__device__ __forceinline__ float fexp(float x)
{
    x = fmaxf(fminf(x, 80.0f), -87.0f);
    const float L2E = 1.4426950408889634f;
    float t = fmaf(x, L2E, 12582912.0f);
    float n = t - 12582912.0f;
    float f = fmaf(x, L2E, -n);
    float p = 1.33335581e-3f;
    p = fmaf(p, f, 9.61812911e-3f);
    p = fmaf(p, f, 5.55041087e-2f);
    p = fmaf(p, f, 2.40226507e-1f);
    p = fmaf(p, f, 6.93147180e-1f);
    p = fmaf(p, f, 1.0f);
    int ni = (int)n;
    ni = max(-126, min(127, ni));
    return p * __int_as_float((ni + 127) << 23);
}

__device__ __forceinline__ void ffma2(ull& c, ull a, ull b)
{
    asm("fma.rn.f32x2 %0, %1, %2, %0;" : "+l"(c) : "l"(a), "l"(b));
}
__device__ __forceinline__ ull dup2(float x)
{
    ull r;
    unsigned u = __float_as_uint(x);
    asm("mov.b64 %0, {%1, %1};" : "=l"(r) : "r"(u));
    return r;
}

// ===========================================================================
// Unified projection launch — 64x128 tiles (TN=8), 920 blocks.
// ===========================================================================
struct ProjArgs {
    const float* W[11];
    const float* X[11];
    float*       C[11];
};

__constant__ int  c_segN  [11] = {2304, 2304,2304, 2304,2304, 576,576, 144,144, 36,36};
__constant__ int  c_segK  [11] = {256, 64,64, 256,256, 512,512, 1024,1024, 2048,2048};
__constant__ int  c_segKs [11] = {1, 1,1, 2,2, 4,4, 8,8, 16,16};
__constant__ int  c_segKch[11] = {256, 64,64, 128,128, 128,128, 128,128, 128,128};
__constant__ int  c_segNt [11] = {18, 18,18, 18,18, 5,5, 2,2, 1,1};
__constant__ int  c_segStart[12] = {0,72,144,216,360,504,584,664,728,792,856,920};
__constant__ long c_segSX [11] = {256L*2304, 64L*2304,64L*2304, 256L*2304,256L*2304,
                                  512L*576,512L*576, 1024L*144,1024L*144, 2048L*36,2048L*36};
__constant__ long c_segSC [11] = {64L*2304, 128L*2304,128L*2304, 128L*2304,128L*2304,
                                  128L*576,128L*576, 128L*144,128L*144, 128L*36,128L*36};

__global__ void __launch_bounds__(256) proj_k(ProjArgs pa)
{
    __shared__ float As[2][16][64];
    __shared__ float Bs[2][16][128];

    const int bid = blockIdx.x;
    int seg = 0;
#pragma unroll
    for (int s = 1; s < 11; s++) if (bid >= c_segStart[s]) seg = s;
    const int local = bid - c_segStart[seg];
    const int ntl = c_segNt[seg];
    const int nt = local % ntl;
    const int rest = local / ntl;
    const int ks = c_segKs[seg];
    const int kz = rest % ks;
    const int b  = rest / ks;

    const int N = c_segN[seg];
    const int K = c_segK[seg];
    const int kchunk = c_segKch[seg];
    const int kbeg = kz * kchunk;
    const int kend = min(K, kbeg + kchunk);
    const int n0 = nt * 128;

    const float* A  = pa.W[seg];
    const float* Bx = pa.X[seg] + (long)b * c_segSX[seg];
    float*       C  = pa.C[seg] + (long)b * c_segSC[seg];

    const int tid = threadIdx.x;
    const int ty = tid >> 4, tx = tid & 15;

    float4 ra, rb[2];
    const int am = tid >> 2, akq = (tid & 3) * 4;

    auto fetchA = [&](int k0) {
        ra = *(const float4*)(A + (long)am * K + k0 + akq);
    };
    auto storeA = [&](int buf) {
        As[buf][akq + 0][am] = ra.x; As[buf][akq + 1][am] = ra.y;
        As[buf][akq + 2][am] = ra.z; As[buf][akq + 3][am] = ra.w;
    };
    auto fetchB = [&](int k0) {
#pragma unroll
        for (int r = 0; r < 2; r++) {
            int e = tid + r * 256;
            int bk = e >> 5, bnq = (e & 31) * 4;
            int gn = n0 + bnq;
            float4 v = {0.f, 0.f, 0.f, 0.f};
            if (gn + 3 < N) v = *(const float4*)(Bx + (long)(k0 + bk) * N + gn);
            rb[r] = v;
        }
    };
    auto storeB = [&](int buf) {
#pragma unroll
        for (int r = 0; r < 2; r++) {
            int e = tid + r * 256;
            int bk = e >> 5, bnq = (e & 31) * 4;
            *(float4*)&Bs[buf][bk][bnq] = rb[r];
        }
    };

    ull acc2[2][8];
#pragma unroll
    for (int i = 0; i < 2; i++)
#pragma unroll
        for (int j = 0; j < 8; j++) acc2[i][j] = 0ULL;

    const int nkt = (kend - kbeg) / 16;

    fetchA(kbeg); fetchB(kbeg);
    storeA(0); storeB(0);
    __syncthreads();

    for (int t = 0; t < nkt; t++) {
        const int cur = t & 1, nxt = cur ^ 1;
        const bool more = (t + 1) < nkt;
        if (more) { fetchA(kbeg + (t + 1) * 16); fetchB(kbeg + (t + 1) * 16); }

#pragma unroll
        for (int kk = 0; kk < 16; kk++) {
            float4 a = *(const float4*)&As[cur][kk][ty * 4];
            const ull* a2 = (const ull*)&a;
            float4 bv0 = *(const float4*)&Bs[cur][kk][tx * 8];
            float4 bv1 = *(const float4*)&Bs[cur][kk][tx * 8 + 4];
            float bf[8] = {bv0.x, bv0.y, bv0.z, bv0.w, bv1.x, bv1.y, bv1.z, bv1.w};
#pragma unroll
            for (int j = 0; j < 8; j++) {
                ull bd = dup2(bf[j]);
                ffma2(acc2[0][j], a2[0], bd);
                ffma2(acc2[1][j], a2[1], bd);
            }
        }

        if (more) { storeA(nxt); storeB(nxt); }
        __syncthreads();
    }

#pragma unroll
    for (int i2 = 0; i2 < 2; i2++) {
        int gmA = ty * 4 + 2 * i2;
#pragma unroll
        for (int j = 0; j < 8; j++) {
            int gn = n0 + tx * 8 + j;
            if (gn >= N) continue;
            float2 w = *(float2*)&acc2[i2][j];
            if (ks > 1) {
                atomicAdd(&C[(long)gmA * N + gn], w.x);
                atomicAdd(&C[(long)(gmA + 1) * N + gn], w.y);
            } else {
                C[(long)gmA * N + gn] = w.x;
                C[(long)(gmA + 1) * N + gn] = w.y;
            }
        }
    }
}

// ---------------------------------------------------------------------------
// Flash attention (validated R14 config — untouched).
// ---------------------------------------------------------------------------
__global__ void __launch_bounds__(256, 3) flash_k(
    const float* __restrict__ T, const float* __restrict__ PG,
    float* __restrict__ O)
{
    extern __shared__ float sm[];
    float (*Tq)[64] = (float(*)[64])(sm);
    float (*Ps)[64] = (float(*)[64])(sm + 4096);
    float (*Gs)[68] = (float(*)[68])(sm + 8192);
    float (*Pt)[68] = (float(*)[68])(sm + 12544);
    __shared__ float redS[8][16][4];

    const int sc = blockIdx.y >> 2;
    const int b  = blockIdx.y & 3;
    const int Mi = d_Mi[sc];
    const int n0 = blockIdx.x * 64;
    const int tid = threadIdx.x;
    const int qg = tid & 15;
    const int mg = tid >> 4;

    const float* Tb = T + (long)b * PLc * NQc;
    const float* Pb = PG + d_PGoff[sc] + (long)b * 2 * PLc * Mi;
    const float* Gb = Pb + (long)PLc * Mi;
    float* Ob = O + (long)sc * OSZ + (long)b * NQc * PLc;

#pragma unroll
    for (int r = 0; r < 4; r++) {
        int e = (tid + r * 256) * 4;
        int k = e >> 6, q = e & 63;
        *(float4*)&Tq[k][q] = *(const float4*)(Tb + (long)k * NQc + n0 + q);
    }

    float Srun[4] = {0.f, 0.f, 0.f, 0.f};
    ull acco[2][4];
#pragma unroll
    for (int i = 0; i < 2; i++)
#pragma unroll
        for (int j = 0; j < 4; j++) acco[i][j] = 0ULL;

    for (int m0 = 0; m0 < Mi; m0 += 64) {
#pragma unroll
        for (int r = 0; r < 4; r++) {
            int e = (tid + r * 256) * 4;
            int k = e >> 6, mm = e & 63;
            float4 v = {0.f, 0.f, 0.f, 0.f};
            if (m0 + mm < Mi) v = *(const float4*)(Pb + (long)k * Mi + m0 + mm);
            *(float4*)&Ps[k][mm] = v;
        }
#pragma unroll
        for (int r = 0; r < 4; r++) {
            int e = tid + r * 256;
            int c = e >> 4, mq = (e & 15) * 4;
            float4 v = {0.f, 0.f, 0.f, 0.f};
            if (m0 + mq < Mi) v = *(const float4*)(Gb + (long)c * Mi + m0 + mq);
            Gs[mq + 0][GSW(mq + 0, c)] = v.x;
            Gs[mq + 1][GSW(mq + 1, c)] = v.y;
            Gs[mq + 2][GSW(mq + 2, c)] = v.z;
            Gs[mq + 3][GSW(mq + 3, c)] = v.w;
        }
        __syncthreads();

        ull accs[2][4];
#pragma unroll
        for (int i = 0; i < 2; i++)
#pragma unroll
            for (int j = 0; j < 4; j++) accs[i][j] = 0ULL;

#pragma unroll 16
        for (int kk = 0; kk < 64; kk++) {
            float4 a = *(const float4*)&Tq[kk][qg * 4];
            const ull* a2 = (const ull*)&a;
            float4 bv = *(const float4*)&Ps[kk][mg * 4];
            const float* bf = (const float*)&bv;
#pragma unroll
            for (int j = 0; j < 4; j++) {
                ull bd = dup2(bf[j]);
                ffma2(accs[0][j], a2[0], bd);
                ffma2(accs[1][j], a2[1], bd);
            }
        }

        float S[4][4];
#pragma unroll
        for (int qp = 0; qp < 2; qp++)
#pragma unroll
            for (int j = 0; j < 4; j++) {
                float2 w = *(float2*)&accs[qp][j];
                S[2 * qp][j] = w.x;
                S[2 * qp + 1][j] = w.y;
            }

#pragma unroll
        for (int j = 0; j < 4; j++) {
            bool ok = (m0 + mg * 4 + j) < Mi;
#pragma unroll
            for (int q = 0; q < 4; q++) {
                float p = ok ? fexp(S[q][j]) : 0.f;
                S[q][j] = p;
                Srun[q] += p;
            }
        }

#pragma unroll
        for (int j = 0; j < 4; j++) {
            float4 v = {S[0][j], S[1][j], S[2][j], S[3][j]};
            *(float4*)&Pt[mg * 4 + j][qg * 4] = v;
        }
        __syncthreads();

#pragma unroll 16
        for (int mm = 0; mm < 64; mm++) {
            float4 a = *(const float4*)&Pt[mm][qg * 4];
            const ull* a2 = (const ull*)&a;
            float4 bv = *(const float4*)&Gs[mm][GSW(mm, mg * 4)];
            const float* bf = (const float*)&bv;
#pragma unroll
            for (int j = 0; j < 4; j++) {
                ull bd = dup2(bf[j]);
                ffma2(acco[0][j], a2[0], bd);
                ffma2(acco[1][j], a2[1], bd);
            }
        }
        __syncthreads();
    }

#pragma unroll
    for (int q = 0; q < 4; q++)
        Srun[q] += __shfl_xor_sync(0xFFFFFFFFu, Srun[q], 16);
    const int w = tid >> 5, lane = tid & 31;
    if (lane < 16) {
#pragma unroll
        for (int q = 0; q < 4; q++) redS[w][lane][q] = Srun[q];
    }
    __syncthreads();

    float inv[4];
#pragma unroll
    for (int q = 0; q < 4; q++) {
        float tot = 0.f;
#pragma unroll
        for (int w2 = 0; w2 < 8; w2++) tot += redS[w2][qg][q];
        inv[q] = 1.0f / tot;
    }

#pragma unroll
    for (int q = 0; q < 4; q++) {
        float4 v;
        float* vv = (float*)&v;
#pragma unroll
        for (int j = 0; j < 4; j++) {
            float2 wv = *(float2*)&acco[q >> 1][j];
            vv[j] = ((q & 1) ? wv.y : wv.x) * inv[q];
        }
        *(float4*)(Ob + ((long)n0 + qg * 4 + q) * PLc + mg * 4) = v;
    }
}

// ---------------------------------------------------------------------------
// Covariance of O_view columns per scale (validated).
// ---------------------------------------------------------------------------
__global__ void __launch_bounds__(256) cov_k(
    const float* __restrict__ O, float* __restrict__ cov)
{
    __shared__ float smv[32][68];
    const int s = blockIdx.y;
    const float* Os = O + (long)s * OSZ;
    float* Cs = cov + s * 4160;
    float* mus = Cs + 4096;

    const int tid = threadIdx.x;
    const int ty = tid >> 4, tx = tid & 15;

    ull acc2[2][4];
#pragma unroll
    for (int i = 0; i < 2; i++)
#pragma unroll
        for (int j = 0; j < 4; j++) acc2[i][j] = 0ULL;
    float mua[4] = {0.f, 0.f, 0.f, 0.f};

    for (int col0 = blockIdx.x * 32; col0 < NB * NQc; col0 += gridDim.x * 32) {
#pragma unroll
        for (int r = 0; r < 8; r++) {
            int e = tid + r * 256;
            int k = e >> 5, cc = e & 31;
            int col = col0 + cc;
            int b = col / NQc, n = col - b * NQc;
            smv[cc][k] = Os[((long)b * 64 + k) * NQc + n];
        }
        __syncthreads();

#pragma unroll
        for (int cc = 0; cc < 32; cc++) {
            float4 a = *(const float4*)&smv[cc][ty * 4];
            const ull* a2 = (const ull*)&a;
            float4 bv = *(const float4*)&smv[cc][tx * 4];
            const float* bf = (const float*)&bv;
#pragma unroll
            for (int j = 0; j < 4; j++) {
                ull bd = dup2(bf[j]);
                ffma2(acc2[0][j], a2[0], bd);
                ffma2(acc2[1][j], a2[1], bd);
            }
            if (tx == 0) { mua[0] += a.x; mua[1] += a.y; mua[2] += a.z; mua[3] += a.w; }
        }
        __syncthreads();
    }

#pragma unroll
    for (int i2 = 0; i2 < 2; i2++)
#pragma unroll
        for (int j = 0; j < 4; j++) {
            float2 w = *(float2*)&acc2[i2][j];
            atomicAdd(&Cs[(ty * 4 + 2 * i2) * 64 + tx * 4 + j], w.x);
            atomicAdd(&Cs[(ty * 4 + 2 * i2 + 1) * 64 + tx * 4 + j], w.y);
        }
    if (tx == 0) {
#pragma unroll
        for (int i = 0; i < 4; i++) atomicAdd(&mus[ty * 4 + i], mua[i]);
    }
}

// ---------------------------------------------------------------------------
// BN stats (validated R14).
// ---------------------------------------------------------------------------
struct StatsArgs { const float* gm[5]; const float* bt[5]; };

__global__ void __launch_bounds__(256) stats_k(
    const float* __restrict__ cov, const float* __restrict__ zw,
    StatsArgs sa, float* __restrict__ Wq, float* __restrict__ cst)
{
    __shared__ float Cs[64][65];
    __shared__ float mus[64];
    __shared__ float zsh[8][64];

    const int s = blockIdx.x;
    const float* Cg = cov + s * 4160;
    const int tid  = threadIdx.x;
    const int w    = tid >> 5;
    const int lane = tid & 31;
    const int c    = blockIdx.y * 8 + w;

#pragma unroll
    for (int it = 0; it < 4; it++) {
        int e = tid * 4 + it * 1024;
        float4 v = *(const float4*)(Cg + e);
        int r = e >> 6, c0 = e & 63;
        Cs[r][c0] = v.x; Cs[r][c0 + 1] = v.y;
        Cs[r][c0 + 2] = v.z; Cs[r][c0 + 3] = v.w;
    }
    if (tid < 64) mus[tid] = Cg[4096 + tid];
    zsh[w][2 * lane]     = zw[(long)c * 64 + 2 * lane];
    zsh[w][2 * lane + 1] = zw[(long)c * 64 + 2 * lane + 1];
    __syncthreads();

    const int k1a = lane, k1b = 32 + lane;
    float za = zsh[w][k1a], zb = zsh[w][k1b];

    float m = fmaf(za, mus[k1a], zb * mus[k1b]);
    float qa = 0.f, qb = 0.f;
#pragma unroll
    for (int k2 = 0; k2 < 64; k2++) {
        float zk = zsh[w][k2];
        qa = fmaf(Cs[k1a][k2], zk, qa);
        qb = fmaf(Cs[k1b][k2], zk, qb);
    }
    float q = fmaf(za, qa, zb * qb);

#pragma unroll
    for (int st = 1; st < 32; st <<= 1) {
        m += __shfl_xor_sync(0xFFFFFFFFu, m, st);
        q += __shfl_xor_sync(0xFFFFFFFFu, q, st);
    }

    const float inv = 1.0f / CNTF;
    m *= inv;
    float var = q * inv - m * m;
    float a = sa.gm[s][c] * rsqrtf(var + 1e-5f);
    if (lane == 0)
        cst[s * CPc + c] = fmaf(-a, m, sa.bt[s][c]);
    Wq[(long)c * 320 + s * 64 + k1a] = a * za;
    Wq[(long)c * 320 + s * 64 + k1b] = a * zb;
}

// ---------------------------------------------------------------------------
// Final GEMM — 128x128 tiles (TM=8): out[b] = Wq[256,320] @ Ostack + cvec.
// ---------------------------------------------------------------------------
__global__ void __launch_bounds__(256) fin_k(
    const float* __restrict__ A, const float* __restrict__ O,
    const float* __restrict__ cst, float* __restrict__ out)
{
    __shared__ float As[2][16][128];
    __shared__ float Bs[2][16][128];

    const int b = blockIdx.z;
    const float* Bb = O + (long)b * (64 * NQc);
    float* Cc = out + (long)b * CPc * NQc;

    const int m0 = blockIdx.y * 128, n0 = blockIdx.x * 128;
    const int tid = threadIdx.x;
    const int ty = tid >> 4, tx = tid & 15;

    float4 ra[2], rb[2];

    auto fetchA = [&](int k0) {
#pragma unroll
        for (int r = 0; r < 2; r++) {
            int e = tid + r * 256;
            int am = e >> 2, akq = (e & 3) * 4;
            ra[r] = *(const float4*)(A + (long)(m0 + am) * 320 + k0 + akq);
        }
    };
    auto storeA = [&](int buf) {
#pragma unroll
        for (int r = 0; r < 2; r++) {
            int e = tid + r * 256;
            int am = e >> 2, akq = (e & 3) * 4;
            As[buf][akq + 0][am] = ra[r].x; As[buf][akq + 1][am] = ra[r].y;
            As[buf][akq + 2][am] = ra[r].z; As[buf][akq + 3][am] = ra[r].w;
        }
    };
    auto fetchB = [&](int k0) {
#pragma unroll
        for (int r = 0; r < 2; r++) {
            int e = tid + r * 256;
            int k = e >> 5, nq = (e & 31) * 4;
            int row = k0 + k;
            long off = (long)(row >> 6) * OSZ + (long)(row & 63) * NQc;
            rb[r] = *(const float4*)(Bb + off + n0 + nq);
        }
    };
    auto storeB = [&](int buf) {
#pragma unroll
        for (int r = 0; r < 2; r++) {
            int e = tid + r * 256;
            int k = e >> 5, nq = (e & 31) * 4;
            *(float4*)&Bs[buf][k][nq] = rb[r];
        }
    };

    ull acc2[4][8];
#pragma unroll
    for (int i = 0; i < 4; i++)
#pragma unroll
        for (int j = 0; j < 8; j++) acc2[i][j] = 0ULL;

    const int nkt = 320 / 16;

    fetchA(0); fetchB(0);
    storeA(0); storeB(0);
    __syncthreads();

    for (int t = 0; t < nkt; t++) {
        const int cur = t & 1, nxt = cur ^ 1;
        const bool more = (t + 1) < nkt;
        if (more) { fetchA((t + 1) * 16); fetchB((t + 1) * 16); }

#pragma unroll
        for (int kk = 0; kk < 16; kk++) {
            float4 a0 = *(const float4*)&As[cur][kk][ty * 8];
            float4 a1 = *(const float4*)&As[cur][kk][ty * 8 + 4];
            const ull* a0p = (const ull*)&a0;
            const ull* a1p = (const ull*)&a1;
            float4 bv0 = *(const float4*)&Bs[cur][kk][tx * 8];
            float4 bv1 = *(const float4*)&Bs[cur][kk][tx * 8 + 4];
            float bf[8] = {bv0.x, bv0.y, bv0.z, bv0.w, bv1.x, bv1.y, bv1.z, bv1.w};
#pragma unroll
            for (int j = 0; j < 8; j++) {
                ull bd = dup2(bf[j]);
                ffma2(acc2[0][j], a0p[0], bd);
                ffma2(acc2[1][j], a0p[1], bd);
                ffma2(acc2[2][j], a1p[0], bd);
                ffma2(acc2[3][j], a1p[1], bd);
            }
        }

        if (more) { storeA(nxt); storeB(nxt); }
        __syncthreads();
    }

#pragma unroll
    for (int i2 = 0; i2 < 4; i2++) {
        int gmA = m0 + ty * 8 + 2 * i2;
        int gmB = gmA + 1;
        float cvA = cst[gmA] + cst[CPc + gmA] + cst[2 * CPc + gmA]
                  + cst[3 * CPc + gmA] + cst[4 * CPc + gmA];
        float cvB = cst[gmB] + cst[CPc + gmB] + cst[2 * CPc + gmB]
                  + cst[3 * CPc + gmB] + cst[4 * CPc + gmB];
#pragma unroll
        for (int j = 0; j < 8; j++) {
            int gn = n0 + tx * 8 + j;
            float2 w = *(float2*)&acc2[i2][j];
            Cc[(long)gmA * NQc + gn] = w.x + cvA;
            Cc[(long)gmB * NQc + gn] = w.y + cvB;
        }
    }
}

// ---------------------------------------------------------------------------
// Host launch
// ---------------------------------------------------------------------------
extern "C" void kernel_launch(void* const* d_in, const int* in_sizes, int n_in,
                              void* d_out, int out_size)
{
    (void)in_sizes; (void)n_in; (void)out_size;

    const float* persp = (const float*)d_in[0];
    const float* resp[5] = {
        (const float*)d_in[1], (const float*)d_in[2], (const float*)d_in[3],
        (const float*)d_in[4], (const float*)d_in[5] };
    const float* t_w = (const float*)d_in[6];
    const float* z_w = (const float*)d_in[7];
    float* out = (float*)d_out;

    static const int MsH[5] = {2304, 2304, 576, 144, 36};
    static const long PGoffH[5] = {0L,
        (long)NB * 128 * 2304,
        (long)NB * 128 * (2304 + 2304),
        (long)NB * 128 * (2304 + 2304 + 576),
        (long)NB * 128 * (2304 + 2304 + 576 + 144)};

    float *T, *PG, *O, *cov, *Wq, *cst;
    cudaGetSymbolAddress((void**)&T,   g_T);
    cudaGetSymbolAddress((void**)&PG,  g_PG);
    cudaGetSymbolAddress((void**)&O,   g_O);
    cudaGetSymbolAddress((void**)&cov, g_cov);
    cudaGetSymbolAddress((void**)&Wq,  g_Wq);
    cudaGetSymbolAddress((void**)&cst, g_cst);

    const int FLASH_SMEM = 16896 * 4;
    cudaFuncSetAttribute(flash_k,
        cudaFuncAttributeMaxDynamicSharedMemorySize, FLASH_SMEM);

    cudaMemsetAsync(PG,  0, PG_TOTAL * 4, 0);
    cudaMemsetAsync(cov, 0, (size_t)5 * 4160 * 4, 0);

    ProjArgs pa;
    pa.W[0] = t_w;  pa.X[0] = persp;  pa.C[0] = T;
    for (int i = 0; i < 5; i++) {
        const float* p_w  = (const float*)d_in[8 + 4 * i];
        const float* g_wt = (const float*)d_in[9 + 4 * i];
        pa.W[1 + 2 * i] = p_w;   pa.X[1 + 2 * i] = resp[i];
        pa.C[1 + 2 * i] = PG + PGoffH[i];
        pa.W[2 + 2 * i] = g_wt;  pa.X[2 + 2 * i] = resp[i];
        pa.C[2 + 2 * i] = PG + PGoffH[i] + (long)PLc * MsH[i];
    }
    proj_k<<<920, 256>>>(pa);

    flash_k<<<dim3(NQc / 64, 5 * NB), 256, FLASH_SMEM>>>(T, PG, O);

    cov_k<<<dim3(48, 5), 256>>>(O, cov);

    StatsArgs sa;
    for (int i = 0; i < 5; i++) {
        sa.gm[i] = (const float*)d_in[10 + 4 * i];
        sa.bt[i] = (const float*)d_in[11 + 4 * i];
    }
    stats_k<<<dim3(5, 32), 256>>>(cov, z_w, sa, Wq, cst);

    fin_k<<<dim3(NQc / 128, CPc / 128, NB), 256>>>(Wq, O, cst, out);
}

// round 16
// speedup vs baseline: 1.2120x; 1.2120x over previous
#include <cuda_runtime.h>
#include <math.h>

#define NB   4
#define CPc  256
#define PLc  64
#define NQc  2304

typedef unsigned long long ull;

__constant__ int  d_Mi[5]    = {2304, 2304, 576, 144, 36};
__constant__ long d_PGoff[5] = {0L,
                                (long)NB * 128 * 2304,
                                (long)NB * 128 * (2304 + 2304),
                                (long)NB * 128 * (2304 + 2304 + 576),
                                (long)NB * 128 * (2304 + 2304 + 576 + 144)};
#define PG_TOTAL ((long)NB * 128 * (2304 + 2304 + 576 + 144 + 36))
#define OSZ ((long)NB * NQc * PLc)
#define CNTF ((float)(NB * NQc))

// Gs column swizzle (16B-preserving)
#define GSW(m, c) ((c) ^ (((((m) >> 2) & 15)) << 2))

// flash y-slice table: 28 slices. sc0/sc1 split into 2 m-chunks (atomic),
// sc2-4 single chunk (direct store).
__constant__ int fy_sc[28] = {0,0,0,0,0,0,0,0, 1,1,1,1,1,1,1,1,
                              2,2,2,2, 3,3,3,3, 4,4,4,4};
__constant__ int fy_b [28] = {0,0,1,1,2,2,3,3, 0,0,1,1,2,2,3,3,
                              0,1,2,3, 0,1,2,3, 0,1,2,3};
__constant__ int fy_m0[28] = {0,1152,0,1152,0,1152,0,1152,
                              0,1152,0,1152,0,1152,0,1152,
                              0,0,0,0, 0,0,0,0, 0,0,0,0};
__constant__ int fy_m1[28] = {1152,2304,1152,2304,1152,2304,1152,2304,
                              1152,2304,1152,2304,1152,2304,1152,2304,
                              576,576,576,576, 144,144,144,144, 36,36,36,36};

// ---------------------------------------------------------------------------
// Scratch
// ---------------------------------------------------------------------------
__device__ float g_T  [NB * PLc * NQc];
__device__ float g_PG [NB * 128 * (2304 + 2304 + 576 + 144 + 36)];
__device__ float g_O  [5 * NB * NQc * PLc];
__device__ float g_sum[2 * NB * NQc];          // heavy-scale exp sums
__device__ float g_cov[5 * 4160];
__device__ float g_Wq [CPc * 320];
__device__ float g_cst[5 * CPc];

// ---------------------------------------------------------------------------
// Helpers
// ---------------------------------------------------------------------------
__device__ __forceinline__ float fexp(float x)
{
    x = fmaxf(fminf(x, 80.0f), -87.0f);
    const float L2E = 1.4426950408889634f;
    float t = fmaf(x, L2E, 12582912.0f);
    float n = t - 12582912.0f;
    float f = fmaf(x, L2E, -n);
    float p = 1.33335581e-3f;
    p = fmaf(p, f, 9.61812911e-3f);
    p = fmaf(p, f, 5.55041087e-2f);
    p = fmaf(p, f, 2.40226507e-1f);
    p = fmaf(p, f, 6.93147180e-1f);
    p = fmaf(p, f, 1.0f);
    int ni = (int)n;
    ni = max(-126, min(127, ni));
    return p * __int_as_float((ni + 127) << 23);
}

__device__ __forceinline__ void ffma2(ull& c, ull a, ull b)
{
    asm("fma.rn.f32x2 %0, %1, %2, %0;" : "+l"(c) : "l"(a), "l"(b));
}
__device__ __forceinline__ ull dup2(float x)
{
    ull r;
    unsigned u = __float_as_uint(x);
    asm("mov.b64 %0, {%1, %1};" : "=l"(r) : "r"(u));
    return r;
}

// ===========================================================================
// Unified projection launch (R14 validated config: 64x64 tiles, 1616 blocks).
// ===========================================================================
struct ProjArgs {
    const float* W[11];
    const float* X[11];
    float*       C[11];
};

__constant__ int  c_segN  [11] = {2304, 2304,2304, 2304,2304, 576,576, 144,144, 36,36};
__constant__ int  c_segK  [11] = {256, 64,64, 256,256, 512,512, 1024,1024, 2048,2048};
__constant__ int  c_segKs [11] = {1, 1,1, 2,2, 4,4, 8,8, 16,16};
__constant__ int  c_segKch[11] = {256, 64,64, 128,128, 128,128, 128,128, 128,128};
__constant__ int  c_segNt [11] = {36, 36,36, 36,36, 9,9, 3,3, 1,1};
__constant__ int  c_segStart[12] = {0,144,288,432,720,1008,1152,1296,1392,1488,1552,1616};
__constant__ long c_segSX [11] = {256L*2304, 64L*2304,64L*2304, 256L*2304,256L*2304,
                                  512L*576,512L*576, 1024L*144,1024L*144, 2048L*36,2048L*36};
__constant__ long c_segSC [11] = {64L*2304, 128L*2304,128L*2304, 128L*2304,128L*2304,
                                  128L*576,128L*576, 128L*144,128L*144, 128L*36,128L*36};

__global__ void __launch_bounds__(256) proj_k(ProjArgs pa)
{
    __shared__ float As[2][16][64];
    __shared__ float Bs[2][16][64];

    const int bid = blockIdx.x;
    int seg = 0;
#pragma unroll
    for (int s = 1; s < 11; s++) if (bid >= c_segStart[s]) seg = s;
    const int local = bid - c_segStart[seg];
    const int ntl = c_segNt[seg];
    const int nt = local % ntl;
    const int rest = local / ntl;
    const int ks = c_segKs[seg];
    const int kz = rest % ks;
    const int b  = rest / ks;

    const int N = c_segN[seg];
    const int K = c_segK[seg];
    const int kchunk = c_segKch[seg];
    const int kbeg = kz * kchunk;
    const int kend = min(K, kbeg + kchunk);
    const int n0 = nt * 64;

    const float* A  = pa.W[seg];
    const float* Bx = pa.X[seg] + (long)b * c_segSX[seg];
    float*       C  = pa.C[seg] + (long)b * c_segSC[seg];

    const int tid = threadIdx.x;
    const int ty = tid >> 4, tx = tid & 15;

    float4 ra, rb;
    const int am = tid >> 2, akq = (tid & 3) * 4;
    const int bk = tid >> 4, bnq = (tid & 15) * 4;
    const int bgn = n0 + bnq;

    auto fetchA = [&](int k0) {
        ra = *(const float4*)(A + (long)am * K + k0 + akq);
    };
    auto storeA = [&](int buf) {
        As[buf][akq + 0][am] = ra.x; As[buf][akq + 1][am] = ra.y;
        As[buf][akq + 2][am] = ra.z; As[buf][akq + 3][am] = ra.w;
    };
    auto fetchB = [&](int k0) {
        rb = make_float4(0.f, 0.f, 0.f, 0.f);
        if (bgn + 3 < N) rb = *(const float4*)(Bx + (long)(k0 + bk) * N + bgn);
    };
    auto storeB = [&](int buf) {
        *(float4*)&Bs[buf][bk][bnq] = rb;
    };

    ull acc2[2][4];
#pragma unroll
    for (int i = 0; i < 2; i++)
#pragma unroll
        for (int j = 0; j < 4; j++) acc2[i][j] = 0ULL;

    const int nkt = (kend - kbeg) / 16;

    fetchA(kbeg); fetchB(kbeg);
    storeA(0); storeB(0);
    __syncthreads();

    for (int t = 0; t < nkt; t++) {
        const int cur = t & 1, nxt = cur ^ 1;
        const bool more = (t + 1) < nkt;
        if (more) { fetchA(kbeg + (t + 1) * 16); fetchB(kbeg + (t + 1) * 16); }

#pragma unroll
        for (int kk = 0; kk < 16; kk++) {
            float4 a = *(const float4*)&As[cur][kk][ty * 4];
            const ull* a2 = (const ull*)&a;
            float4 bv = *(const float4*)&Bs[cur][kk][tx * 4];
            const float* bf = (const float*)&bv;
#pragma unroll
            for (int j = 0; j < 4; j++) {
                ull bd = dup2(bf[j]);
                ffma2(acc2[0][j], a2[0], bd);
                ffma2(acc2[1][j], a2[1], bd);
            }
        }

        if (more) { storeA(nxt); storeB(nxt); }
        __syncthreads();
    }

#pragma unroll
    for (int i2 = 0; i2 < 2; i2++) {
        int gmA = ty * 4 + 2 * i2;
#pragma unroll
        for (int j = 0; j < 4; j++) {
            int gn = n0 + tx * 4 + j;
            if (gn >= N) continue;
            float2 w = *(float2*)&acc2[i2][j];
            if (ks > 1) {
                atomicAdd(&C[(long)gmA * N + gn], w.x);
                atomicAdd(&C[(long)(gmA + 1) * N + gn], w.y);
            } else {
                C[(long)gmA * N + gn] = w.x;
                C[(long)(gmA + 1) * N + gn] = w.y;
            }
        }
    }
}

// ---------------------------------------------------------------------------
// Flash attention with split-M for heavy scales. Direct exp => unnormalized O
// and exp-sums are additive across m-chunks (atomicAdd), normalized later.
// ---------------------------------------------------------------------------
__global__ void __launch_bounds__(256, 3) flash_k(
    const float* __restrict__ T, const float* __restrict__ PG,
    float* __restrict__ O, float* __restrict__ gsum)
{
    extern __shared__ float sm[];
    float (*Tq)[64] = (float(*)[64])(sm);
    float (*Ps)[64] = (float(*)[64])(sm + 4096);
    float (*Gs)[68] = (float(*)[68])(sm + 8192);
    float (*Pt)[68] = (float(*)[68])(sm + 12544);
    __shared__ float redS[8][16][4];

    const int yy = blockIdx.y;
    const int sc = fy_sc[yy];
    const int b  = fy_b[yy];
    const int mBeg = fy_m0[yy];
    const int mEnd = fy_m1[yy];
    const bool atom = (sc < 2);
    const int Mi = d_Mi[sc];
    const int n0 = blockIdx.x * 64;
    const int tid = threadIdx.x;
    const int qg = tid & 15;
    const int mg = tid >> 4;

    const float* Tb = T + (long)b * PLc * NQc;
    const float* Pb = PG + d_PGoff[sc] + (long)b * 2 * PLc * Mi;
    const float* Gb = Pb + (long)PLc * Mi;
    float* Ob = O + (long)sc * OSZ + (long)b * NQc * PLc;

#pragma unroll
    for (int r = 0; r < 4; r++) {
        int e = (tid + r * 256) * 4;
        int k = e >> 6, q = e & 63;
        *(float4*)&Tq[k][q] = *(const float4*)(Tb + (long)k * NQc + n0 + q);
    }

    float Srun[4] = {0.f, 0.f, 0.f, 0.f};
    ull acco[2][4];
#pragma unroll
    for (int i = 0; i < 2; i++)
#pragma unroll
        for (int j = 0; j < 4; j++) acco[i][j] = 0ULL;

    for (int m0 = mBeg; m0 < mEnd; m0 += 64) {
#pragma unroll
        for (int r = 0; r < 4; r++) {
            int e = (tid + r * 256) * 4;
            int k = e >> 6, mm = e & 63;
            float4 v = {0.f, 0.f, 0.f, 0.f};
            if (m0 + mm < mEnd) v = *(const float4*)(Pb + (long)k * Mi + m0 + mm);
            *(float4*)&Ps[k][mm] = v;
        }
#pragma unroll
        for (int r = 0; r < 4; r++) {
            int e = tid + r * 256;
            int c = e >> 4, mq = (e & 15) * 4;
            float4 v = {0.f, 0.f, 0.f, 0.f};
            if (m0 + mq < mEnd) v = *(const float4*)(Gb + (long)c * Mi + m0 + mq);
            Gs[mq + 0][GSW(mq + 0, c)] = v.x;
            Gs[mq + 1][GSW(mq + 1, c)] = v.y;
            Gs[mq + 2][GSW(mq + 2, c)] = v.z;
            Gs[mq + 3][GSW(mq + 3, c)] = v.w;
        }
        __syncthreads();

        ull accs[2][4];
#pragma unroll
        for (int i = 0; i < 2; i++)
#pragma unroll
            for (int j = 0; j < 4; j++) accs[i][j] = 0ULL;

#pragma unroll 16
        for (int kk = 0; kk < 64; kk++) {
            float4 a = *(const float4*)&Tq[kk][qg * 4];
            const ull* a2 = (const ull*)&a;
            float4 bv = *(const float4*)&Ps[kk][mg * 4];
            const float* bf = (const float*)&bv;
#pragma unroll
            for (int j = 0; j < 4; j++) {
                ull bd = dup2(bf[j]);
                ffma2(accs[0][j], a2[0], bd);
                ffma2(accs[1][j], a2[1], bd);
            }
        }

        float S[4][4];
#pragma unroll
        for (int qp = 0; qp < 2; qp++)
#pragma unroll
            for (int j = 0; j < 4; j++) {
                float2 w = *(float2*)&accs[qp][j];
                S[2 * qp][j] = w.x;
                S[2 * qp + 1][j] = w.y;
            }

#pragma unroll
        for (int j = 0; j < 4; j++) {
            bool ok = (m0 + mg * 4 + j) < mEnd;
#pragma unroll
            for (int q = 0; q < 4; q++) {
                float p = ok ? fexp(S[q][j]) : 0.f;
                S[q][j] = p;
                Srun[q] += p;
            }
        }

#pragma unroll
        for (int j = 0; j < 4; j++) {
            float4 v = {S[0][j], S[1][j], S[2][j], S[3][j]};
            *(float4*)&Pt[mg * 4 + j][qg * 4] = v;
        }
        __syncthreads();

#pragma unroll 16
        for (int mm = 0; mm < 64; mm++) {
            float4 a = *(const float4*)&Pt[mm][qg * 4];
            const ull* a2 = (const ull*)&a;
            float4 bv = *(const float4*)&Gs[mm][GSW(mm, mg * 4)];
            const float* bf = (const float*)&bv;
#pragma unroll
            for (int j = 0; j < 4; j++) {
                ull bd = dup2(bf[j]);
                ffma2(acco[0][j], a2[0], bd);
                ffma2(acco[1][j], a2[1], bd);
            }
        }
        __syncthreads();
    }

    // ---- Srun reduce ----
#pragma unroll
    for (int q = 0; q < 4; q++)
        Srun[q] += __shfl_xor_sync(0xFFFFFFFFu, Srun[q], 16);
    const int w = tid >> 5, lane = tid & 31;
    if (lane < 16) {
#pragma unroll
        for (int q = 0; q < 4; q++) redS[w][lane][q] = Srun[q];
    }
    __syncthreads();

    float tot[4];
#pragma unroll
    for (int q = 0; q < 4; q++) {
        float t = 0.f;
#pragma unroll
        for (int w2 = 0; w2 < 8; w2++) t += redS[w2][qg][q];
        tot[q] = t;
    }

    if (atom) {
        // heavy scale: accumulate unnormalized O and partial sums
        if (mg == 0) {
            long sbase = (long)(sc * NB + b) * NQc + n0;
#pragma unroll
            for (int q = 0; q < 4; q++)
                atomicAdd(&gsum[sbase + qg * 4 + q], tot[q]);
        }
#pragma unroll
        for (int q = 0; q < 4; q++) {
            float* rowp = Ob + ((long)n0 + qg * 4 + q) * PLc + mg * 4;
#pragma unroll
            for (int j = 0; j < 4; j++) {
                float2 wv = *(float2*)&acco[q >> 1][j];
                atomicAdd(&rowp[j], (q & 1) ? wv.y : wv.x);
            }
        }
    } else {
#pragma unroll
        for (int q = 0; q < 4; q++) {
            float inv = 1.0f / tot[q];
            float4 v;
            float* vv = (float*)&v;
#pragma unroll
            for (int j = 0; j < 4; j++) {
                float2 wv = *(float2*)&acco[q >> 1][j];
                vv[j] = ((q & 1) ? wv.y : wv.x) * inv;
            }
            *(float4*)(Ob + ((long)n0 + qg * 4 + q) * PLc + mg * 4) = v;
        }
    }
}

// ---------------------------------------------------------------------------
// Normalize heavy-scale O rows by 1/sum. Covers scales 0,1 (first 2*OSZ).
// ---------------------------------------------------------------------------
__global__ void __launch_bounds__(256) norm_k(
    float* __restrict__ O, const float* __restrict__ gsum)
{
    long i4 = (long)blockIdx.x * 256 + threadIdx.x;   // float4 index
    long f = i4 * 4;
    float inv = 1.0f / gsum[f >> 6];
    float4 v = *(float4*)(O + f);
    v.x *= inv; v.y *= inv; v.z *= inv; v.w *= inv;
    *(float4*)(O + f) = v;
}

// ---------------------------------------------------------------------------
// Covariance of O_view columns per scale (validated).
// ---------------------------------------------------------------------------
__global__ void __launch_bounds__(256) cov_k(
    const float* __restrict__ O, float* __restrict__ cov)
{
    __shared__ float smv[32][68];
    const int s = blockIdx.y;
    const float* Os = O + (long)s * OSZ;
    float* Cs = cov + s * 4160;
    float* mus = Cs + 4096;

    const int tid = threadIdx.x;
    const int ty = tid >> 4, tx = tid & 15;

    ull acc2[2][4];
#pragma unroll
    for (int i = 0; i < 2; i++)
#pragma unroll
        for (int j = 0; j < 4; j++) acc2[i][j] = 0ULL;
    float mua[4] = {0.f, 0.f, 0.f, 0.f};

    for (int col0 = blockIdx.x * 32; col0 < NB * NQc; col0 += gridDim.x * 32) {
#pragma unroll
        for (int r = 0; r < 8; r++) {
            int e = tid + r * 256;
            int k = e >> 5, cc = e & 31;
            int col = col0 + cc;
            int b = col / NQc, n = col - b * NQc;
            smv[cc][k] = Os[((long)b * 64 + k) * NQc + n];
        }
        __syncthreads();

#pragma unroll
        for (int cc = 0; cc < 32; cc++) {
            float4 a = *(const float4*)&smv[cc][ty * 4];
            const ull* a2 = (const ull*)&a;
            float4 bv = *(const float4*)&smv[cc][tx * 4];
            const float* bf = (const float*)&bv;
#pragma unroll
            for (int j = 0; j < 4; j++) {
                ull bd = dup2(bf[j]);
                ffma2(acc2[0][j], a2[0], bd);
                ffma2(acc2[1][j], a2[1], bd);
            }
            if (tx == 0) { mua[0] += a.x; mua[1] += a.y; mua[2] += a.z; mua[3] += a.w; }
        }
        __syncthreads();
    }

#pragma unroll
    for (int i2 = 0; i2 < 2; i2++)
#pragma unroll
        for (int j = 0; j < 4; j++) {
            float2 w = *(float2*)&acc2[i2][j];
            atomicAdd(&Cs[(ty * 4 + 2 * i2) * 64 + tx * 4 + j], w.x);
            atomicAdd(&Cs[(ty * 4 + 2 * i2 + 1) * 64 + tx * 4 + j], w.y);
        }
    if (tx == 0) {
#pragma unroll
        for (int i = 0; i < 4; i++) atomicAdd(&mus[ty * 4 + i], mua[i]);
    }
}

// ---------------------------------------------------------------------------
// BN stats (validated R14).
// ---------------------------------------------------------------------------
struct StatsArgs { const float* gm[5]; const float* bt[5]; };

__global__ void __launch_bounds__(256) stats_k(
    const float* __restrict__ cov, const float* __restrict__ zw,
    StatsArgs sa, float* __restrict__ Wq, float* __restrict__ cst)
{
    __shared__ float Cs[64][65];
    __shared__ float mus[64];
    __shared__ float zsh[8][64];

    const int s = blockIdx.x;
    const float* Cg = cov + s * 4160;
    const int tid  = threadIdx.x;
    const int w    = tid >> 5;
    const int lane = tid & 31;
    const int c    = blockIdx.y * 8 + w;

#pragma unroll
    for (int it = 0; it < 4; it++) {
        int e = tid * 4 + it * 1024;
        float4 v = *(const float4*)(Cg + e);
        int r = e >> 6, c0 = e & 63;
        Cs[r][c0] = v.x; Cs[r][c0 + 1] = v.y;
        Cs[r][c0 + 2] = v.z; Cs[r][c0 + 3] = v.w;
    }
    if (tid < 64) mus[tid] = Cg[4096 + tid];
    zsh[w][2 * lane]     = zw[(long)c * 64 + 2 * lane];
    zsh[w][2 * lane + 1] = zw[(long)c * 64 + 2 * lane + 1];
    __syncthreads();

    const int k1a = lane, k1b = 32 + lane;
    float za = zsh[w][k1a], zb = zsh[w][k1b];

    float m = fmaf(za, mus[k1a], zb * mus[k1b]);
    float qa = 0.f, qb = 0.f;
#pragma unroll
    for (int k2 = 0; k2 < 64; k2++) {
        float zk = zsh[w][k2];
        qa = fmaf(Cs[k1a][k2], zk, qa);
        qb = fmaf(Cs[k1b][k2], zk, qb);
    }
    float q = fmaf(za, qa, zb * qb);

#pragma unroll
    for (int st = 1; st < 32; st <<= 1) {
        m += __shfl_xor_sync(0xFFFFFFFFu, m, st);
        q += __shfl_xor_sync(0xFFFFFFFFu, q, st);
    }

    const float inv = 1.0f / CNTF;
    m *= inv;
    float var = q * inv - m * m;
    float a = sa.gm[s][c] * rsqrtf(var + 1e-5f);
    if (lane == 0)
        cst[s * CPc + c] = fmaf(-a, m, sa.bt[s][c]);
    Wq[(long)c * 320 + s * 64 + k1a] = a * za;
    Wq[(long)c * 320 + s * 64 + k1b] = a * zb;
}

// ---------------------------------------------------------------------------
// Final GEMM (R14 validated config: 64x128 tiles).
// ---------------------------------------------------------------------------
__global__ void __launch_bounds__(256) fin_k(
    const float* __restrict__ A, const float* __restrict__ O,
    const float* __restrict__ cst, float* __restrict__ out)
{
    __shared__ float As[2][16][64];
    __shared__ float Bs[2][16][128];

    const int b = blockIdx.z;
    const float* Bb = O + (long)b * (64 * NQc);
    float* Cc = out + (long)b * CPc * NQc;

    const int m0 = blockIdx.y * 64, n0 = blockIdx.x * 128;
    const int tid = threadIdx.x;
    const int ty = tid >> 4, tx = tid & 15;

    float4 ra, rb[2];
    const int am = tid >> 2, akq = (tid & 3) * 4;

    auto fetchA = [&](int k0) {
        ra = *(const float4*)(A + (long)(m0 + am) * 320 + k0 + akq);
    };
    auto storeA = [&](int buf) {
        As[buf][akq + 0][am] = ra.x; As[buf][akq + 1][am] = ra.y;
        As[buf][akq + 2][am] = ra.z; As[buf][akq + 3][am] = ra.w;
    };
    auto fetchB = [&](int k0) {
#pragma unroll
        for (int r = 0; r < 2; r++) {
            int e = tid + r * 256;
            int k = e >> 5, nq = (e & 31) * 4;
            int row = k0 + k;
            long off = (long)(row >> 6) * OSZ + (long)(row & 63) * NQc;
            rb[r] = *(const float4*)(Bb + off + n0 + nq);
        }
    };
    auto storeB = [&](int buf) {
#pragma unroll
        for (int r = 0; r < 2; r++) {
            int e = tid + r * 256;
            int k = e >> 5, nq = (e & 31) * 4;
            *(float4*)&Bs[buf][k][nq] = rb[r];
        }
    };

    ull acc2[2][8];
#pragma unroll
    for (int i = 0; i < 2; i++)
#pragma unroll
        for (int j = 0; j < 8; j++) acc2[i][j] = 0ULL;

    const int nkt = 320 / 16;

    fetchA(0); fetchB(0);
    storeA(0); storeB(0);
    __syncthreads();

    for (int t = 0; t < nkt; t++) {
        const int cur = t & 1, nxt = cur ^ 1;
        const bool more = (t + 1) < nkt;
        if (more) { fetchA((t + 1) * 16); fetchB((t + 1) * 16); }

#pragma unroll
        for (int kk = 0; kk < 16; kk++) {
            float4 a = *(const float4*)&As[cur][kk][ty * 4];
            const ull* a2 = (const ull*)&a;
            float4 bv0 = *(const float4*)&Bs[cur][kk][tx * 8];
            float4 bv1 = *(const float4*)&Bs[cur][kk][tx * 8 + 4];
            float bf[8] = {bv0.x, bv0.y, bv0.z, bv0.w, bv1.x, bv1.y, bv1.z, bv1.w};
#pragma unroll
            for (int j = 0; j < 8; j++) {
                ull bd = dup2(bf[j]);
                ffma2(acc2[0][j], a2[0], bd);
                ffma2(acc2[1][j], a2[1], bd);
            }
        }

        if (more) { storeA(nxt); storeB(nxt); }
        __syncthreads();
    }

#pragma unroll
    for (int i2 = 0; i2 < 2; i2++) {
        int gmA = m0 + ty * 4 + 2 * i2;
        int gmB = gmA + 1;
        float cvA = cst[gmA] + cst[CPc + gmA] + cst[2 * CPc + gmA]
                  + cst[3 * CPc + gmA] + cst[4 * CPc + gmA];
        float cvB = cst[gmB] + cst[CPc + gmB] + cst[2 * CPc + gmB]
                  + cst[3 * CPc + gmB] + cst[4 * CPc + gmB];
#pragma unroll
        for (int j = 0; j < 8; j++) {
            int gn = n0 + tx * 8 + j;
            float2 w = *(float2*)&acc2[i2][j];
            Cc[(long)gmA * NQc + gn] = w.x + cvA;
            Cc[(long)gmB * NQc + gn] = w.y + cvB;
        }
    }
}

// ---------------------------------------------------------------------------
// Host launch
// ---------------------------------------------------------------------------
extern "C" void kernel_launch(void* const* d_in, const int* in_sizes, int n_in,
                              void* d_out, int out_size)
{
    (void)in_sizes; (void)n_in; (void)out_size;

    const float* persp = (const float*)d_in[0];
    const float* resp[5] = {
        (const float*)d_in[1], (const float*)d_in[2], (const float*)d_in[3],
        (const float*)d_in[4], (const float*)d_in[5] };
    const float* t_w = (const float*)d_in[6];
    const float* z_w = (const float*)d_in[7];
    float* out = (float*)d_out;

    static const int MsH[5] = {2304, 2304, 576, 144, 36};
    static const long PGoffH[5] = {0L,
        (long)NB * 128 * 2304,
        (long)NB * 128 * (2304 + 2304),
        (long)NB * 128 * (2304 + 2304 + 576),
        (long)NB * 128 * (2304 + 2304 + 576 + 144)};

    float *T, *PG, *O, *gsum, *cov, *Wq, *cst;
    cudaGetSymbolAddress((void**)&T,    g_T);
    cudaGetSymbolAddress((void**)&PG,   g_PG);
    cudaGetSymbolAddress((void**)&O,    g_O);
    cudaGetSymbolAddress((void**)&gsum, g_sum);
    cudaGetSymbolAddress((void**)&cov,  g_cov);
    cudaGetSymbolAddress((void**)&Wq,   g_Wq);
    cudaGetSymbolAddress((void**)&cst,  g_cst);

    const int FLASH_SMEM = 16896 * 4;
    cudaFuncSetAttribute(flash_k,
        cudaFuncAttributeMaxDynamicSharedMemorySize, FLASH_SMEM);

    cudaMemsetAsync(PG,   0, PG_TOTAL * 4, 0);
    cudaMemsetAsync(cov,  0, (size_t)5 * 4160 * 4, 0);
    cudaMemsetAsync(O,    0, (size_t)2 * OSZ * 4, 0);     // heavy-scale region
    cudaMemsetAsync(gsum, 0, (size_t)2 * NB * NQc * 4, 0);

    ProjArgs pa;
    pa.W[0] = t_w;  pa.X[0] = persp;  pa.C[0] = T;
    for (int i = 0; i < 5; i++) {
        const float* p_w  = (const float*)d_in[8 + 4 * i];
        const float* g_wt = (const float*)d_in[9 + 4 * i];
        pa.W[1 + 2 * i] = p_w;   pa.X[1 + 2 * i] = resp[i];
        pa.C[1 + 2 * i] = PG + PGoffH[i];
        pa.W[2 + 2 * i] = g_wt;  pa.X[2 + 2 * i] = resp[i];
        pa.C[2 + 2 * i] = PG + PGoffH[i] + (long)PLc * MsH[i];
    }
    proj_k<<<1616, 256>>>(pa);

    // flash: 28 y-slices (heavy scales split in 2 m-chunks)
    flash_k<<<dim3(NQc / 64, 28), 256, FLASH_SMEM>>>(T, PG, O, gsum);

    // normalize heavy-scale O
    norm_k<<<(unsigned)(2 * OSZ / 4 / 256), 256>>>(O, gsum);

    cov_k<<<dim3(48, 5), 256>>>(O, cov);

    StatsArgs sa;
    for (int i = 0; i < 5; i++) {
        sa.gm[i] = (const float*)d_in[10 + 4 * i];
        sa.bt[i] = (const float*)d_in[11 + 4 * i];
    }
    stats_k<<<dim3(5, 32), 256>>>(cov, z_w, sa, Wq, cst);

    fin_k<<<dim3(NQc / 128, CPc / 64, NB), 256>>>(Wq, O, cst, out);
}